// round 5
// baseline (speedup 1.0000x reference)
#include <cuda_runtime.h>
#include <cmath>

// Problem constants
#define NN_  8192
#define DD_  768
#define HH1_ 512
#define HH2_ 256

// ---------------- device scratch (static globals: allocation-guard legal) ----
__device__ float g_S [67108864];          // 8192*8192  (256 MiB) attention scores / P'
__device__ float g_Q [NN_ * DD_];
__device__ float g_K [NN_ * DD_];
__device__ float g_V [NN_ * DD_];         // X @ Wg
__device__ float g_Y [NN_ * DD_];         // X + M
__device__ float g_H1[NN_ * HH1_];
__device__ float g_H2[NN_ * HH2_];
__device__ float g_G [NN_];
__device__ float g_rowM[NN_];
__device__ float g_rowS[NN_];

// ---------------- math helpers ---------------------------------------------
__device__ __forceinline__ float gelu_exact(float x) {
    return 0.5f * x * (1.0f + erff(x * 0.70710678118654752440f));
}
__device__ __forceinline__ float softplus_(float x) {
    // stable log1p(exp(x))
    return fmaxf(x, 0.0f) + log1pf(expf(-fabsf(x)));
}

// ---------------- 128x128x8 double-buffered SGEMM ---------------------------
// C[M,N] = epi( scale * A[M,K] @ op(B) )
//   TRANSB=false: B is [K,N] row-major;  TRANSB=true: B is [N,K] row-major (C=A*B^T)
//   EPI 0: C = acc*scale
//   EPI 1: C = gelu(acc + bias[col])
//   EPI 2: C = addsrc[row,col] + gelu(acc + bias[col])
// Requires: M%128==0, N%128==0, K%8==0. All satisfied for every call here.
template<bool TRANSB, int EPI>
__global__ __launch_bounds__(256, 2)
void sgemm128(const float* __restrict__ A, const float* __restrict__ B,
              float* __restrict__ C, int M, int N, int K,
              const float* __restrict__ bias, const float* __restrict__ addsrc,
              float scale)
{
    __shared__ float As[2][8][128];
    __shared__ float Bs[2][8][128];

    const int tid = threadIdx.x;
    const int bx = blockIdx.x, by = blockIdx.y;
    const int rowBase = by * 128, colBase = bx * 128;

    // A tile loader: 128 rows x 8 k; one float4 per thread
    const int aRow = tid >> 1;             // 0..127
    const int aCol = (tid & 1) * 4;        // 0 or 4
    const float* aPtr = A + (size_t)(rowBase + aRow) * K + aCol;

    // B tile loader
    int bRow, bCol;
    const float* bPtr;
    if (TRANSB) {                          // B[N,K]: tile 128 n-rows x 8 k
        bRow = tid >> 1; bCol = (tid & 1) * 4;
        bPtr = B + (size_t)(colBase + bRow) * K + bCol;
    } else {                               // B[K,N]: tile 8 k-rows x 128 cols
        bRow = tid >> 5; bCol = (tid & 31) * 4;
        bPtr = B + (size_t)bRow * N + colBase + bCol;
    }

    const int ty = tid >> 4, tx = tid & 15;

    float acc[8][8];
#pragma unroll
    for (int i = 0; i < 8; i++)
#pragma unroll
        for (int j = 0; j < 8; j++) acc[i][j] = 0.0f;

    // prologue: load tile 0
    {
        float4 av = *(const float4*)(aPtr);
        As[0][aCol + 0][aRow] = av.x; As[0][aCol + 1][aRow] = av.y;
        As[0][aCol + 2][aRow] = av.z; As[0][aCol + 3][aRow] = av.w;
        if (TRANSB) {
            float4 bv = *(const float4*)(bPtr);
            Bs[0][bCol + 0][bRow] = bv.x; Bs[0][bCol + 1][bRow] = bv.y;
            Bs[0][bCol + 2][bRow] = bv.z; Bs[0][bCol + 3][bRow] = bv.w;
        } else {
            float4 bv = *(const float4*)(bPtr);
            *(float4*)&Bs[0][bRow][bCol] = bv;
        }
    }
    __syncthreads();

    const int ntiles = K / 8;
    for (int t = 0; t < ntiles; t++) {
        const int cur = t & 1, nxt = cur ^ 1;
        float4 an, bn;
        const bool more = (t + 1 < ntiles);
        if (more) {
            an = *(const float4*)(aPtr + (t + 1) * 8);
            bn = TRANSB ? *(const float4*)(bPtr + (t + 1) * 8)
                        : *(const float4*)(bPtr + (size_t)(t + 1) * 8 * N);
        }
#pragma unroll
        for (int k = 0; k < 8; k++) {
            float4 a0 = *(const float4*)&As[cur][k][ty * 8];
            float4 a1 = *(const float4*)&As[cur][k][ty * 8 + 4];
            float4 b0 = *(const float4*)&Bs[cur][k][tx * 8];
            float4 b1 = *(const float4*)&Bs[cur][k][tx * 8 + 4];
            float aa[8] = {a0.x, a0.y, a0.z, a0.w, a1.x, a1.y, a1.z, a1.w};
            float bb[8] = {b0.x, b0.y, b0.z, b0.w, b1.x, b1.y, b1.z, b1.w};
#pragma unroll
            for (int i = 0; i < 8; i++)
#pragma unroll
                for (int j = 0; j < 8; j++)
                    acc[i][j] = fmaf(aa[i], bb[j], acc[i][j]);
        }
        if (more) {
            As[nxt][aCol + 0][aRow] = an.x; As[nxt][aCol + 1][aRow] = an.y;
            As[nxt][aCol + 2][aRow] = an.z; As[nxt][aCol + 3][aRow] = an.w;
            if (TRANSB) {
                Bs[nxt][bCol + 0][bRow] = bn.x; Bs[nxt][bCol + 1][bRow] = bn.y;
                Bs[nxt][bCol + 2][bRow] = bn.z; Bs[nxt][bCol + 3][bRow] = bn.w;
            } else {
                *(float4*)&Bs[nxt][bRow][bCol] = bn;
            }
        }
        __syncthreads();
    }

    // epilogue
    const int crow = rowBase + ty * 8;
    const int ccol = colBase + tx * 8;
#pragma unroll
    for (int i = 0; i < 8; i++) {
        float* cp = C + (size_t)(crow + i) * N + ccol;
        float vals[8];
#pragma unroll
        for (int j = 0; j < 8; j++) {
            float v = acc[i][j] * scale;
            if (EPI == 1) {
                v = gelu_exact(v + bias[ccol + j]);
            } else if (EPI == 2) {
                v = addsrc[(size_t)(crow + i) * N + ccol + j] + gelu_exact(v + bias[ccol + j]);
            }
            vals[j] = v;
        }
        *(float4*)(cp)     = make_float4(vals[0], vals[1], vals[2], vals[3]);
        *(float4*)(cp + 4) = make_float4(vals[4], vals[5], vals[6], vals[7]);
    }
}

// ---------------- NIG head final: r = H2 @ Wh + bh, then nonlinearities ------
// One warp per row. H2 is [N,256], Wh is [256,4] row-major (float4 rows).
__global__ void head_final(const float* __restrict__ H2, const float* __restrict__ Wh,
                           const float* __restrict__ bh, float* __restrict__ out,
                           int outOff, float* __restrict__ Gbuf,
                           const float* __restrict__ gamp, int N)
{
    const int warp = threadIdx.x >> 5, lane = threadIdx.x & 31;
    const int row = blockIdx.x * 8 + warp;

    float4 acc = make_float4(0.f, 0.f, 0.f, 0.f);
    const float* h = H2 + (size_t)row * HH2_ + lane * 8;
#pragma unroll
    for (int i = 0; i < 8; i++) {
        float hv = h[i];
        float4 w = *(const float4*)&Wh[(lane * 8 + i) * 4];
        acc.x = fmaf(hv, w.x, acc.x);
        acc.y = fmaf(hv, w.y, acc.y);
        acc.z = fmaf(hv, w.z, acc.z);
        acc.w = fmaf(hv, w.w, acc.w);
    }
#pragma unroll
    for (int off = 16; off > 0; off >>= 1) {
        acc.x += __shfl_xor_sync(0xffffffffu, acc.x, off);
        acc.y += __shfl_xor_sync(0xffffffffu, acc.y, off);
        acc.z += __shfl_xor_sync(0xffffffffu, acc.z, off);
        acc.w += __shfl_xor_sync(0xffffffffu, acc.w, off);
    }
    if (lane == 0) {
        float r0 = acc.x + bh[0], r1 = acc.y + bh[1];
        float r2 = acc.z + bh[2], r3 = acc.w + bh[3];
        float mu = r0;
        float v  = softplus_(r1) + 1e-6f;
        float a  = softplus_(r2) + 1.0f + 1e-6f;
        float b  = softplus_(r3) + 1e-6f;
        out[outOff + 0 * N + row] = mu;
        out[outOff + 1 * N + row] = v;
        out[outOff + 2 * N + row] = a;
        out[outOff + 3 * N + row] = b;
        if (Gbuf) {
            float u0  = b / fmaxf(a - 1.0f, 1e-8f);
            float sig = 1.0f / (1.0f + expf(-u0));
            Gbuf[row] = 1.0f - gamp[0] * sig;
        }
    }
}

// ---------------- per-row softmax stats with G weighting ---------------------
// Computes m_i = max_j S_ij ; Z = sum e^{S-m} ; W = sum e^{S-m} G_j ;
// then s_i = (G_i/Z) / max(G_i*W/Z, 1e-8). Stores (m_i, s_i).
__global__ void softmax_stats(const float* __restrict__ S, const float* __restrict__ G,
                              float* __restrict__ rowM, float* __restrict__ rowSc, int N)
{
    const int row = blockIdx.x;
    const float* s = S + (size_t)row * N;
    float m = -INFINITY, Z = 0.f, W = 0.f;
    for (int j = threadIdx.x; j < N; j += 256) {
        float x = s[j];
        float g = G[j];
        if (x > m) {
            float e = expf(m - x);   // e=0 when m==-inf
            Z *= e; W *= e; m = x;
        }
        float p = expf(x - m);
        Z += p; W = fmaf(p, g, W);
    }
    __shared__ float sm[256], sZ[256], sW[256];
    sm[threadIdx.x] = m; sZ[threadIdx.x] = Z; sW[threadIdx.x] = W;
    __syncthreads();
    for (int off = 128; off > 0; off >>= 1) {
        if (threadIdx.x < off) {
            float m1 = sm[threadIdx.x],       Z1 = sZ[threadIdx.x],       W1 = sW[threadIdx.x];
            float m2 = sm[threadIdx.x + off], Z2 = sZ[threadIdx.x + off], W2 = sW[threadIdx.x + off];
            float mn = fmaxf(m1, m2);
            float e1 = expf(m1 - mn), e2 = expf(m2 - mn);
            sm[threadIdx.x] = mn;
            sZ[threadIdx.x] = Z1 * e1 + Z2 * e2;
            sW[threadIdx.x] = W1 * e1 + W2 * e2;
        }
        __syncthreads();
    }
    if (threadIdx.x == 0) {
        float mF = sm[0], ZF = sZ[0], WF = sW[0];
        float Gi = G[row];
        float rowsum = Gi * WF / ZF;                 // G_i * sum_j A_ij G_j
        float sc = (Gi / ZF) / fmaxf(rowsum, 1e-8f); // matches Dinv clamp exactly
        rowM[row] = mF; rowSc[row] = sc;
    }
}

// ---------------- in-place rescale: S <- exp(S-m)*G_j*s_i --------------------
__global__ void rescale_kernel(float* __restrict__ S, const float* __restrict__ G,
                               const float* __restrict__ rowM, const float* __restrict__ rowSc,
                               int N)
{
    const int row = blockIdx.y;
    const int j = blockIdx.x * 1024 + threadIdx.x * 4;
    const float m = rowM[row], sc = rowSc[row];
    float4* p = (float4*)(S + (size_t)row * N + j);
    float4 v = *p;
    const float4 g = *(const float4*)(G + j);
    v.x = expf(v.x - m) * g.x * sc;
    v.y = expf(v.y - m) * g.y * sc;
    v.z = expf(v.z - m) * g.z * sc;
    v.w = expf(v.w - m) * g.w * sc;
    *p = v;
}

// ---------------- launcher ---------------------------------------------------
extern "C" void kernel_launch(void* const* d_in, const int* in_sizes, int n_in,
                              void* d_out, int out_size)
{
    (void)in_sizes; (void)n_in; (void)out_size;

    const float* X    = (const float*)d_in[0];
    const float* Wq   = (const float*)d_in[1];
    const float* Wk   = (const float*)d_in[2];
    const float* Wg   = (const float*)d_in[3];
    const float* bg   = (const float*)d_in[4];
    const float* gam  = (const float*)d_in[5];
    const float* ihW1 = (const float*)d_in[6];
    const float* ihb1 = (const float*)d_in[7];
    const float* ihW2 = (const float*)d_in[8];
    const float* ihb2 = (const float*)d_in[9];
    const float* ihWh = (const float*)d_in[10];
    const float* ihbh = (const float*)d_in[11];
    const float* fhW1 = (const float*)d_in[12];
    const float* fhb1 = (const float*)d_in[13];
    const float* fhW2 = (const float*)d_in[14];
    const float* fhb2 = (const float*)d_in[15];
    const float* fhWh = (const float*)d_in[16];
    const float* fhbh = (const float*)d_in[17];
    float* out = (float*)d_out;

    float *S, *Q, *Kp, *V, *Y, *H1b, *H2b, *G, *rM, *rS;
    cudaGetSymbolAddress((void**)&S,   g_S);
    cudaGetSymbolAddress((void**)&Q,   g_Q);
    cudaGetSymbolAddress((void**)&Kp,  g_K);
    cudaGetSymbolAddress((void**)&V,   g_V);
    cudaGetSymbolAddress((void**)&Y,   g_Y);
    cudaGetSymbolAddress((void**)&H1b, g_H1);
    cudaGetSymbolAddress((void**)&H2b, g_H2);
    cudaGetSymbolAddress((void**)&G,   g_G);
    cudaGetSymbolAddress((void**)&rM,  g_rowM);
    cudaGetSymbolAddress((void**)&rS,  g_rowS);

    const int N = NN_, D = DD_, H1 = HH1_, H2 = HH2_;
    const float invSqrtD = 1.0f / sqrtf((float)D);

    // ---- head 1 on X -> m0,v0,a0,b0 (out[0..4N)) and gate G ----
    sgemm128<false, 1><<<dim3(H1 / 128, N / 128), 256>>>(X,   ihW1, H1b, N, H1, D,  ihb1, nullptr, 1.0f);
    sgemm128<false, 1><<<dim3(H2 / 128, N / 128), 256>>>(H1b, ihW2, H2b, N, H2, H1, ihb2, nullptr, 1.0f);
    head_final<<<N / 8, 256>>>(H2b, ihWh, ihbh, out, 0, G, gam, N);

    // ---- projections ----
    sgemm128<false, 0><<<dim3(D / 128, N / 128), 256>>>(X, Wq, Q,  N, D, D, nullptr, nullptr, 1.0f);
    sgemm128<false, 0><<<dim3(D / 128, N / 128), 256>>>(X, Wk, Kp, N, D, D, nullptr, nullptr, 1.0f);
    sgemm128<false, 0><<<dim3(D / 128, N / 128), 256>>>(X, Wg, V,  N, D, D, nullptr, nullptr, 1.0f);

    // ---- S = Q K^T / sqrt(D) ----
    sgemm128<true, 0><<<dim3(N / 128, N / 128), 256>>>(Q, Kp, S, N, N, D, nullptr, nullptr, invSqrtD);

    // ---- softmax stats + gated row normalization folded into S ----
    softmax_stats<<<N, 256>>>(S, G, rM, rS, N);
    rescale_kernel<<<dim3(N / 1024, N), 256>>>(S, G, rM, rS, N);

    // ---- Y = X + gelu(P' @ V + bg) ----
    sgemm128<false, 2><<<dim3(D / 128, N / 128), 256>>>(S, V, Y, N, D, N, bg, X, 1.0f);

    // ---- head 2 on Y -> mu,v,al,be (out[4N..8N)) ----
    sgemm128<false, 1><<<dim3(H1 / 128, N / 128), 256>>>(Y,   fhW1, H1b, N, H1, D,  fhb1, nullptr, 1.0f);
    sgemm128<false, 1><<<dim3(H2 / 128, N / 128), 256>>>(H1b, fhW2, H2b, N, H2, H1, fhb2, nullptr, 1.0f);
    head_final<<<N / 8, 256>>>(H2b, fhWh, fhbh, out, 4 * N, nullptr, gam, N);
}

// round 7
// speedup vs baseline: 2.6233x; 2.6233x over previous
#include <cuda_runtime.h>
#include <cmath>

// Problem constants
#define NN_  8192
#define DD_  768
#define HH1_ 512
#define HH2_ 256

// ---------------- device scratch (static globals: allocation-guard legal) ----
__device__ float g_S [67108864];          // 8192*8192  (256 MiB) attention scores / P'
__device__ float g_Q [NN_ * DD_];
__device__ float g_K [NN_ * DD_];
__device__ float g_V [NN_ * DD_];         // X @ Wg
__device__ float g_Y [NN_ * DD_];         // X + M
__device__ float g_H1[NN_ * HH1_];
__device__ float g_H2[NN_ * HH2_];
__device__ float g_G [NN_];
__device__ float g_rowM[NN_];
__device__ float g_rowS[NN_];

// ---------------- math helpers ---------------------------------------------
__device__ __forceinline__ float gelu_exact(float x) {
    return 0.5f * x * (1.0f + erff(x * 0.70710678118654752440f));
}
__device__ __forceinline__ float softplus_(float x) {
    return fmaxf(x, 0.0f) + log1pf(expf(-fabsf(x)));
}
__device__ __forceinline__ unsigned f2tf(float f) {
    unsigned r;
    asm("cvt.rna.tf32.f32 %0, %1;" : "=r"(r) : "f"(f));
    return r;
}
__device__ __forceinline__ void mma_tf32(float* c, const unsigned* a, const unsigned* b) {
    asm volatile(
        "mma.sync.aligned.m16n8k8.row.col.f32.tf32.tf32.f32 "
        "{%0,%1,%2,%3}, {%4,%5,%6,%7}, {%8,%9}, {%0,%1,%2,%3};"
        : "+f"(c[0]), "+f"(c[1]), "+f"(c[2]), "+f"(c[3])
        : "r"(a[0]), "r"(a[1]), "r"(a[2]), "r"(a[3]), "r"(b[0]), "r"(b[1]));
}

// ---------------- 128x128x16 double-buffered TF32 tensor-core GEMM ----------
// C[M,Nn] = epi( scale * A[M,K] @ op(B) )
//   TRANSB=false: B is [K,Nn] row-major;  TRANSB=true: B is [Nn,K] row-major (C=A*B^T)
//   EPI 0: C = acc*scale
//   EPI 1: C = gelu(acc + bias[col])
//   EPI 2: C = addsrc[row,col] + gelu(acc + bias[col])
// Requires: M%128==0, Nn%128==0, K%16==0.
template<bool TRANSB, int EPI>
__global__ __launch_bounds__(256)
void tgemm(const float* __restrict__ A, const float* __restrict__ B,
           float* __restrict__ C, int M, int Nn, int K,
           const float* __restrict__ bias, const float* __restrict__ addsrc,
           float scale)
{
    constexpr int KT = 16;
    // A tile: [m=128][k=16] pad to 20 (conflict-free frag reads: (20m+k)%32 unique)
    __shared__ unsigned As[2][128][20];
    // B tile: non-trans [k=16][n=128] pad 136 ((136k+n)%32 = 8k+n unique);
    //         trans     [n=128][k=16] pad 20 (same pattern as A)
    constexpr int BR = TRANSB ? 128 : 16;
    constexpr int BS = TRANSB ? 20  : 136;
    __shared__ unsigned Bs[2][BR][BS];

    const int tid  = threadIdx.x;
    const int lane = tid & 31;
    const int warp = tid >> 5;
    const int warpM = (warp & 1) * 64;   // 2 warps along M
    const int warpN = (warp >> 1) * 32;  // 4 warps along N
    const int rowBase = blockIdx.y * 128, colBase = blockIdx.x * 128;

    // A loader: 2 float4 per thread. row0 = tid>>2 (0..63), second at row0+64.
    const int ldRow = tid >> 2;
    const int ldK   = (tid & 3) * 4;
    const float* gA = A + (size_t)(rowBase + ldRow) * K + ldK;

    // B loader
    const float* gB;
    int bK = 0, bN = 0;
    if (TRANSB) {
        gB = B + (size_t)(colBase + ldRow) * K + ldK;       // same mapping as A
    } else {
        bK = tid >> 5;            // 0..7, second at +8
        bN = (tid & 31) * 4;      // 0..124
        gB = B + (size_t)bK * Nn + colBase + bN;
    }

    float acc[4][4][4];
#pragma unroll
    for (int i = 0; i < 4; i++)
#pragma unroll
        for (int j = 0; j < 4; j++)
#pragma unroll
            for (int q = 0; q < 4; q++) acc[i][j][q] = 0.0f;

    float4 ra0, ra1, rb0, rb1;

    // prologue: load tile 0
    ra0 = *(const float4*)(gA);
    ra1 = *(const float4*)(gA + (size_t)64 * K);
    if (TRANSB) {
        rb0 = *(const float4*)(gB);
        rb1 = *(const float4*)(gB + (size_t)64 * K);
    } else {
        rb0 = *(const float4*)(gB);
        rb1 = *(const float4*)(gB + (size_t)8 * Nn);
    }
    {
        uint4 u;
        u.x = f2tf(ra0.x); u.y = f2tf(ra0.y); u.z = f2tf(ra0.z); u.w = f2tf(ra0.w);
        *(uint4*)&As[0][ldRow][ldK] = u;
        u.x = f2tf(ra1.x); u.y = f2tf(ra1.y); u.z = f2tf(ra1.z); u.w = f2tf(ra1.w);
        *(uint4*)&As[0][ldRow + 64][ldK] = u;
        if (TRANSB) {
            u.x = f2tf(rb0.x); u.y = f2tf(rb0.y); u.z = f2tf(rb0.z); u.w = f2tf(rb0.w);
            *(uint4*)&Bs[0][ldRow][ldK] = u;
            u.x = f2tf(rb1.x); u.y = f2tf(rb1.y); u.z = f2tf(rb1.z); u.w = f2tf(rb1.w);
            *(uint4*)&Bs[0][ldRow + 64][ldK] = u;
        } else {
            u.x = f2tf(rb0.x); u.y = f2tf(rb0.y); u.z = f2tf(rb0.z); u.w = f2tf(rb0.w);
            *(uint4*)&Bs[0][bK][bN] = u;
            u.x = f2tf(rb1.x); u.y = f2tf(rb1.y); u.z = f2tf(rb1.z); u.w = f2tf(rb1.w);
            *(uint4*)&Bs[0][bK + 8][bN] = u;
        }
    }
    __syncthreads();

    const int r0 = lane >> 2;      // 0..7
    const int c0 = lane & 3;       // 0..3
    const int ntiles = K / KT;

    for (int t = 0; t < ntiles; t++) {
        const int cur = t & 1, nxt = cur ^ 1;
        const bool more = (t + 1 < ntiles);
        if (more) {
            ra0 = *(const float4*)(gA + (t + 1) * KT);
            ra1 = *(const float4*)(gA + (t + 1) * KT + (size_t)64 * K);
            if (TRANSB) {
                rb0 = *(const float4*)(gB + (t + 1) * KT);
                rb1 = *(const float4*)(gB + (t + 1) * KT + (size_t)64 * K);
            } else {
                rb0 = *(const float4*)(gB + (size_t)(t + 1) * KT * Nn);
                rb1 = *(const float4*)(gB + (size_t)((t + 1) * KT + 8) * Nn);
            }
        }
        // compute on cur buffer: 2 k-steps of 8
#pragma unroll
        for (int ks = 0; ks < 2; ks++) {
            const int k0 = ks * 8;
            unsigned af[4][4];
#pragma unroll
            for (int i = 0; i < 4; i++) {
                const int m0 = warpM + i * 16;
                af[i][0] = As[cur][m0 + r0    ][k0 + c0    ];
                af[i][1] = As[cur][m0 + r0 + 8][k0 + c0    ];
                af[i][2] = As[cur][m0 + r0    ][k0 + c0 + 4];
                af[i][3] = As[cur][m0 + r0 + 8][k0 + c0 + 4];
            }
            unsigned bf[4][2];
#pragma unroll
            for (int j = 0; j < 4; j++) {
                const int n0 = warpN + j * 8;
                if (TRANSB) {
                    bf[j][0] = Bs[cur][n0 + r0][k0 + c0    ];
                    bf[j][1] = Bs[cur][n0 + r0][k0 + c0 + 4];
                } else {
                    bf[j][0] = Bs[cur][k0 + c0    ][n0 + r0];
                    bf[j][1] = Bs[cur][k0 + c0 + 4][n0 + r0];
                }
            }
#pragma unroll
            for (int i = 0; i < 4; i++)
#pragma unroll
                for (int j = 0; j < 4; j++)
                    mma_tf32(acc[i][j], af[i], bf[j]);
        }
        if (more) {
            uint4 u;
            u.x = f2tf(ra0.x); u.y = f2tf(ra0.y); u.z = f2tf(ra0.z); u.w = f2tf(ra0.w);
            *(uint4*)&As[nxt][ldRow][ldK] = u;
            u.x = f2tf(ra1.x); u.y = f2tf(ra1.y); u.z = f2tf(ra1.z); u.w = f2tf(ra1.w);
            *(uint4*)&As[nxt][ldRow + 64][ldK] = u;
            if (TRANSB) {
                u.x = f2tf(rb0.x); u.y = f2tf(rb0.y); u.z = f2tf(rb0.z); u.w = f2tf(rb0.w);
                *(uint4*)&Bs[nxt][ldRow][ldK] = u;
                u.x = f2tf(rb1.x); u.y = f2tf(rb1.y); u.z = f2tf(rb1.z); u.w = f2tf(rb1.w);
                *(uint4*)&Bs[nxt][ldRow + 64][ldK] = u;
            } else {
                u.x = f2tf(rb0.x); u.y = f2tf(rb0.y); u.z = f2tf(rb0.z); u.w = f2tf(rb0.w);
                *(uint4*)&Bs[nxt][bK][bN] = u;
                u.x = f2tf(rb1.x); u.y = f2tf(rb1.y); u.z = f2tf(rb1.z); u.w = f2tf(rb1.w);
                *(uint4*)&Bs[nxt][bK + 8][bN] = u;
            }
        }
        __syncthreads();
    }

    // epilogue: fragment layout m16n8 -> c0:(r0, 2c0) c1:(r0, 2c0+1) c2/c3: row+8
    const int cc = (lane & 3) * 2;
#pragma unroll
    for (int i = 0; i < 4; i++) {
        const int gr = rowBase + warpM + i * 16 + r0;
#pragma unroll
        for (int j = 0; j < 4; j++) {
            const int gc = colBase + warpN + j * 8 + cc;
#pragma unroll
            for (int half = 0; half < 2; half++) {
                const int row = gr + half * 8;
                float v0 = acc[i][j][half * 2 + 0] * scale;
                float v1 = acc[i][j][half * 2 + 1] * scale;
                if (EPI == 1) {
                    v0 = gelu_exact(v0 + bias[gc]);
                    v1 = gelu_exact(v1 + bias[gc + 1]);
                } else if (EPI == 2) {
                    const float* ap = addsrc + (size_t)row * Nn + gc;
                    v0 = ap[0] + gelu_exact(v0 + bias[gc]);
                    v1 = ap[1] + gelu_exact(v1 + bias[gc + 1]);
                }
                *(float2*)(C + (size_t)row * Nn + gc) = make_float2(v0, v1);
            }
        }
    }
}

// ---------------- NIG head final: r = H2 @ Wh + bh, then nonlinearities ------
__global__ void head_final(const float* __restrict__ H2, const float* __restrict__ Wh,
                           const float* __restrict__ bh, float* __restrict__ out,
                           int outOff, float* __restrict__ Gbuf,
                           const float* __restrict__ gamp, int N)
{
    const int warp = threadIdx.x >> 5, lane = threadIdx.x & 31;
    const int row = blockIdx.x * 8 + warp;

    float4 acc = make_float4(0.f, 0.f, 0.f, 0.f);
    const float* h = H2 + (size_t)row * HH2_ + lane * 8;
#pragma unroll
    for (int i = 0; i < 8; i++) {
        float hv = h[i];
        float4 w = *(const float4*)&Wh[(lane * 8 + i) * 4];
        acc.x = fmaf(hv, w.x, acc.x);
        acc.y = fmaf(hv, w.y, acc.y);
        acc.z = fmaf(hv, w.z, acc.z);
        acc.w = fmaf(hv, w.w, acc.w);
    }
#pragma unroll
    for (int off = 16; off > 0; off >>= 1) {
        acc.x += __shfl_xor_sync(0xffffffffu, acc.x, off);
        acc.y += __shfl_xor_sync(0xffffffffu, acc.y, off);
        acc.z += __shfl_xor_sync(0xffffffffu, acc.z, off);
        acc.w += __shfl_xor_sync(0xffffffffu, acc.w, off);
    }
    if (lane == 0) {
        float mu = acc.x + bh[0];
        float v  = softplus_(acc.y + bh[1]) + 1e-6f;
        float a  = softplus_(acc.z + bh[2]) + 1.0f + 1e-6f;
        float b  = softplus_(acc.w + bh[3]) + 1e-6f;
        out[outOff + 0 * N + row] = mu;
        out[outOff + 1 * N + row] = v;
        out[outOff + 2 * N + row] = a;
        out[outOff + 3 * N + row] = b;
        if (Gbuf) {
            float u0  = b / fmaxf(a - 1.0f, 1e-8f);
            float sig = 1.0f / (1.0f + expf(-u0));
            Gbuf[row] = 1.0f - gamp[0] * sig;
        }
    }
}

// ---------------- per-row softmax stats with G weighting ---------------------
__global__ void softmax_stats(const float* __restrict__ S, const float* __restrict__ G,
                              float* __restrict__ rowM, float* __restrict__ rowSc, int N)
{
    const int row = blockIdx.x;
    const float* s = S + (size_t)row * N;
    float m = -INFINITY, Z = 0.f, W = 0.f;
    for (int j = threadIdx.x * 4; j < N; j += 1024) {
        float4 x = *(const float4*)(s + j);
        float4 g = *(const float4*)(G + j);
        float xv[4] = {x.x, x.y, x.z, x.w};
        float gv[4] = {g.x, g.y, g.z, g.w};
#pragma unroll
        for (int q = 0; q < 4; q++) {
            float xx = xv[q];
            if (xx > m) {
                float e = expf(m - xx);
                Z *= e; W *= e; m = xx;
            }
            float p = expf(xx - m);
            Z += p; W = fmaf(p, gv[q], W);
        }
    }
    __shared__ float sm[256], sZ[256], sW[256];
    sm[threadIdx.x] = m; sZ[threadIdx.x] = Z; sW[threadIdx.x] = W;
    __syncthreads();
    for (int off = 128; off > 0; off >>= 1) {
        if (threadIdx.x < off) {
            float m1 = sm[threadIdx.x],       Z1 = sZ[threadIdx.x],       W1 = sW[threadIdx.x];
            float m2 = sm[threadIdx.x + off], Z2 = sZ[threadIdx.x + off], W2 = sW[threadIdx.x + off];
            float mn = fmaxf(m1, m2);
            float e1 = expf(m1 - mn), e2 = expf(m2 - mn);
            sm[threadIdx.x] = mn;
            sZ[threadIdx.x] = Z1 * e1 + Z2 * e2;
            sW[threadIdx.x] = W1 * e1 + W2 * e2;
        }
        __syncthreads();
    }
    if (threadIdx.x == 0) {
        float mF = sm[0], ZF = sZ[0], WF = sW[0];
        float Gi = G[row];
        float rowsum = Gi * WF / ZF;
        float sc = (Gi / ZF) / fmaxf(rowsum, 1e-8f);
        rowM[row] = mF; rowSc[row] = sc;
    }
}

// ---------------- in-place rescale: S <- exp(S-m)*G_j*s_i --------------------
__global__ void rescale_kernel(float* __restrict__ S, const float* __restrict__ G,
                               const float* __restrict__ rowM, const float* __restrict__ rowSc,
                               int N)
{
    const int row = blockIdx.y;
    const int j = blockIdx.x * 1024 + threadIdx.x * 4;
    const float m = rowM[row], sc = rowSc[row];
    float4* p = (float4*)(S + (size_t)row * N + j);
    float4 v = *p;
    const float4 g = *(const float4*)(G + j);
    v.x = expf(v.x - m) * g.x * sc;
    v.y = expf(v.y - m) * g.y * sc;
    v.z = expf(v.z - m) * g.z * sc;
    v.w = expf(v.w - m) * g.w * sc;
    *p = v;
}

// ---------------- launcher ---------------------------------------------------
extern "C" void kernel_launch(void* const* d_in, const int* in_sizes, int n_in,
                              void* d_out, int out_size)
{
    (void)in_sizes; (void)n_in; (void)out_size;

    const float* X    = (const float*)d_in[0];
    const float* Wq   = (const float*)d_in[1];
    const float* Wk   = (const float*)d_in[2];
    const float* Wg   = (const float*)d_in[3];
    const float* bg   = (const float*)d_in[4];
    const float* gam  = (const float*)d_in[5];
    const float* ihW1 = (const float*)d_in[6];
    const float* ihb1 = (const float*)d_in[7];
    const float* ihW2 = (const float*)d_in[8];
    const float* ihb2 = (const float*)d_in[9];
    const float* ihWh = (const float*)d_in[10];
    const float* ihbh = (const float*)d_in[11];
    const float* fhW1 = (const float*)d_in[12];
    const float* fhb1 = (const float*)d_in[13];
    const float* fhW2 = (const float*)d_in[14];
    const float* fhb2 = (const float*)d_in[15];
    const float* fhWh = (const float*)d_in[16];
    const float* fhbh = (const float*)d_in[17];
    float* out = (float*)d_out;

    float *S, *Q, *Kp, *V, *Y, *H1b, *H2b, *G, *rM, *rS;
    cudaGetSymbolAddress((void**)&S,   g_S);
    cudaGetSymbolAddress((void**)&Q,   g_Q);
    cudaGetSymbolAddress((void**)&Kp,  g_K);
    cudaGetSymbolAddress((void**)&V,   g_V);
    cudaGetSymbolAddress((void**)&Y,   g_Y);
    cudaGetSymbolAddress((void**)&H1b, g_H1);
    cudaGetSymbolAddress((void**)&H2b, g_H2);
    cudaGetSymbolAddress((void**)&G,   g_G);
    cudaGetSymbolAddress((void**)&rM,  g_rowM);
    cudaGetSymbolAddress((void**)&rS,  g_rowS);

    const int N = NN_, D = DD_, H1 = HH1_, H2 = HH2_;
    const float invSqrtD = 1.0f / sqrtf((float)D);

    // ---- head 1 on X -> m0,v0,a0,b0 (out[0..4N)) and gate G ----
    tgemm<false, 1><<<dim3(H1 / 128, N / 128), 256>>>(X,   ihW1, H1b, N, H1, D,  ihb1, nullptr, 1.0f);
    tgemm<false, 1><<<dim3(H2 / 128, N / 128), 256>>>(H1b, ihW2, H2b, N, H2, H1, ihb2, nullptr, 1.0f);
    head_final<<<N / 8, 256>>>(H2b, ihWh, ihbh, out, 0, G, gam, N);

    // ---- projections ----
    tgemm<false, 0><<<dim3(D / 128, N / 128), 256>>>(X, Wq, Q,  N, D, D, nullptr, nullptr, 1.0f);
    tgemm<false, 0><<<dim3(D / 128, N / 128), 256>>>(X, Wk, Kp, N, D, D, nullptr, nullptr, 1.0f);
    tgemm<false, 0><<<dim3(D / 128, N / 128), 256>>>(X, Wg, V,  N, D, D, nullptr, nullptr, 1.0f);

    // ---- S = Q K^T / sqrt(D) ----
    tgemm<true, 0><<<dim3(N / 128, N / 128), 256>>>(Q, Kp, S, N, N, D, nullptr, nullptr, invSqrtD);

    // ---- softmax stats + gated row normalization folded into S ----
    softmax_stats<<<N, 256>>>(S, G, rM, rS, N);
    rescale_kernel<<<dim3(N / 1024, N), 256>>>(S, G, rM, rS, N);

    // ---- Y = X + gelu(P' @ V + bg) ----
    tgemm<false, 2><<<dim3(D / 128, N / 128), 256>>>(S, V, Y, N, D, N, bg, X, 1.0f);

    // ---- head 2 on Y -> mu,v,al,be (out[4N..8N)) ----
    tgemm<false, 1><<<dim3(H1 / 128, N / 128), 256>>>(Y,   fhW1, H1b, N, H1, D,  fhb1, nullptr, 1.0f);
    tgemm<false, 1><<<dim3(H2 / 128, N / 128), 256>>>(H1b, fhW2, H2b, N, H2, H1, fhb2, nullptr, 1.0f);
    head_final<<<N / 8, 256>>>(H2b, fhWh, fhbh, out, 4 * N, nullptr, gam, N);
}